// round 4
// baseline (speedup 1.0000x reference)
#include <cuda_runtime.h>
#include <math.h>

#define BATCH 64
#define SEQ   512
#define EMB   256
#define HID   512
#define G4    2048   // 4*HID
#define NCLS  4
#define NCTA  128    // persistent CTAs, one per SM (<=148)

typedef unsigned long long u64;

// Scratch (allocation-free rule: __device__ globals)
__device__ float g_xg[(size_t)SEQ * G4 * BATCH];   // [t][n][b], n = gate*H + j  (256 MiB)
// h stored pair-interleaved: element (k,b) at (k>>1)*128 + b*2 + (k&1)
__device__ float g_h[2][HID * BATCH];
__device__ unsigned int g_bar;

__device__ __forceinline__ float sigmoidf_(float x) {
    return 1.0f / (1.0f + __expf(-x));
}

__device__ __forceinline__ u64 fma2(u64 a, u64 b, u64 c) {
    u64 d;
    asm("fma.rn.f32x2 %0, %1, %2, %3;" : "=l"(d) : "l"(a), "l"(b), "l"(c));
    return d;
}
__device__ __forceinline__ u64 pack2(float x, float y) {
    u64 r;
    asm("mov.b64 %0, {%1, %2};" : "=l"(r) : "f"(x), "f"(y));
    return r;
}
__device__ __forceinline__ float2 unpack2(u64 v) {
    float2 r;
    asm("mov.b64 {%0, %1}, %2;" : "=f"(r.x), "=f"(r.y) : "l"(v));
    return r;
}

__global__ void init_state() {
    int i = blockIdx.x * blockDim.x + threadIdx.x;
    g_h[0][i] = 0.0f;
    if (i == 0) g_bar = 0u;
}

// xg[t][n][b] = sum_k emb[tok(t,b)][k] * W_ih[n][k] + b_ih[n] + b_hh[n]
// Tiled fp32 GEMM: 64x64 tile, BK=16, 256 threads, 4x4 micro-tile, FFMA2 inner.
__global__ void xg_gemm(const int* __restrict__ x, const float* __restrict__ emb,
                        const float* __restrict__ W_ih,
                        const float* __restrict__ b_ih, const float* __restrict__ b_hh) {
    __shared__ float As[16][64];
    __shared__ float Bs[16][64];
    __shared__ int   tok_s[64];

    const int m0  = blockIdx.y * 64;
    const int n0  = blockIdx.x * 64;
    const int tid = threadIdx.x;        // 256
    const int tx  = tid & 15, ty = tid >> 4;
    const int r   = tid >> 2, q  = tid & 3;

    if (tid < 64) {
        int m = m0 + tid;
        tok_s[tid] = x[(m & (BATCH - 1)) * SEQ + (m >> 6)];
    }
    __syncthreads();

    const size_t arow = (size_t)tok_s[r] * EMB;
    const size_t brow = (size_t)(n0 + r) * EMB;

    u64 acc[4][2] = {};   // acc[i][jp] = packed (j = jp*2, jp*2+1)
    for (int kt = 0; kt < EMB; kt += 16) {
        float4 av = *(const float4*)(emb  + arow + kt + q * 4);
        float4 bv = *(const float4*)(W_ih + brow + kt + q * 4);
        As[q*4+0][r] = av.x; As[q*4+1][r] = av.y; As[q*4+2][r] = av.z; As[q*4+3][r] = av.w;
        Bs[q*4+0][r] = bv.x; Bs[q*4+1][r] = bv.y; Bs[q*4+2][r] = bv.z; Bs[q*4+3][r] = bv.w;
        __syncthreads();
        #pragma unroll
        for (int k = 0; k < 16; k++) {
            float4 a = *(const float4*)&As[k][ty * 4];
            ulonglong2 bq = *(const ulonglong2*)&Bs[k][tx * 4];
            u64 a0 = pack2(a.x, a.x), a1 = pack2(a.y, a.y);
            u64 a2 = pack2(a.z, a.z), a3 = pack2(a.w, a.w);
            acc[0][0] = fma2(a0, bq.x, acc[0][0]); acc[0][1] = fma2(a0, bq.y, acc[0][1]);
            acc[1][0] = fma2(a1, bq.x, acc[1][0]); acc[1][1] = fma2(a1, bq.y, acc[1][1]);
            acc[2][0] = fma2(a2, bq.x, acc[2][0]); acc[2][1] = fma2(a2, bq.y, acc[2][1]);
            acc[3][0] = fma2(a3, bq.x, acc[3][0]); acc[3][1] = fma2(a3, bq.y, acc[3][1]);
        }
        __syncthreads();
    }

    // unpack to scalars
    float accs[4][4];
    #pragma unroll
    for (int i = 0; i < 4; i++) {
        float2 lo = unpack2(acc[i][0]);
        float2 hi = unpack2(acc[i][1]);
        accs[i][0] = lo.x; accs[i][1] = lo.y; accs[i][2] = hi.x; accs[i][3] = hi.y;
    }

    // write [t][n][b] layout; within this block t is constant, b = ty*4+i.
    const int t = m0 >> 6;
    #pragma unroll
    for (int j = 0; j < 4; j++) {
        int n = n0 + tx * 4 + j;
        float bias = b_ih[n] + b_hh[n];
        float4 v = make_float4(accs[0][j] + bias, accs[1][j] + bias,
                               accs[2][j] + bias, accs[3][j] + bias);
        *(float4*)&g_xg[((size_t)t * G4 + n) * BATCH + ty * 4] = v;
    }
}

// Persistent recurrence: 128 CTAs (1/SM), each owns 4 hidden units (16 W_hh rows
// in smem). FFMA2 inner loop; h pair-interleaved in smem and gmem.
__global__ void __launch_bounds__(256, 1)
lstm_persistent(const float* __restrict__ W_hh) {
    extern __shared__ float sm[];
    float* h_s = sm;                    // pair-interleaved [k2][b][2] = 128 KiB
    float* W_s = sm + HID * BATCH;      // [16][512]: row = gate*4 + unit

    const int tid = threadIdx.x;        // 256
    const int cta = blockIdx.x;
    const int b = tid & 63;
    const int r = tid >> 6;             // local unit 0..3
    const int j0 = cta * 4;
    const int j  = j0 + r;

    // One-time: load this CTA's 16 W_hh rows into smem.
    for (int row = 0; row < 16; row++) {
        int g = row >> 2, u = row & 3;
        const float* src = W_hh + (size_t)(g * HID + j0 + u) * HID;
        for (int k = tid; k < HID; k += 256)
            W_s[row * HID + k] = src[k];
    }
    float c_reg = 0.0f;
    __syncthreads();

    const u64* hs64 = (const u64*)h_s;
    const ulonglong2* Wp = (const ulonglong2*)W_s;   // [16][128]
    const int wrow0 = (0 * 4 + r) * 128;
    const int wrow1 = (1 * 4 + r) * 128;
    const int wrow2 = (2 * 4 + r) * 128;
    const int wrow3 = (3 * 4 + r) * 128;
    const int hout_idx = (j >> 1) * 128 + b * 2 + (j & 1);

    for (int t = 0; t < SEQ; t++) {
        const int rb = t & 1;

        // Prefetch xg early (independent of h) — overlaps the broadcast copy.
        const float* xg = g_xg + ((size_t)t * G4 + j) * BATCH + b;
        float xi = __ldcg(xg + 0 * HID * BATCH);
        float xf = __ldcg(xg + 1 * HID * BATCH);
        float xG = __ldcg(xg + 2 * HID * BATCH);
        float xo = __ldcg(xg + 3 * HID * BATCH);

        // Cooperative broadcast load of h (bypass L1: other SMs wrote it).
        const float4* src = (const float4*)g_h[rb];
        float4* dst = (float4*)h_s;
        #pragma unroll
        for (int i = 0; i < 32; i++)
            dst[tid + i * 256] = __ldcg(src + tid + i * 256);
        __syncthreads();

        u64 aA0 = 0, aA1 = 0, aA2 = 0, aA3 = 0;
        u64 aB0 = 0, aB1 = 0, aB2 = 0, aB3 = 0;
        #pragma unroll 8
        for (int k4 = 0; k4 < 128; k4++) {
            u64 hA = hs64[(2 * k4) * 64 + b];
            u64 hB = hs64[(2 * k4 + 1) * 64 + b];
            ulonglong2 w0 = Wp[wrow0 + k4];
            ulonglong2 w1 = Wp[wrow1 + k4];
            ulonglong2 w2 = Wp[wrow2 + k4];
            ulonglong2 w3 = Wp[wrow3 + k4];
            aA0 = fma2(w0.x, hA, aA0); aB0 = fma2(w0.y, hB, aB0);
            aA1 = fma2(w1.x, hA, aA1); aB1 = fma2(w1.y, hB, aB1);
            aA2 = fma2(w2.x, hA, aA2); aB2 = fma2(w2.y, hB, aB2);
            aA3 = fma2(w3.x, hA, aA3); aB3 = fma2(w3.y, hB, aB3);
        }
        float2 s0a = unpack2(aA0), s0b = unpack2(aB0);
        float2 s1a = unpack2(aA1), s1b = unpack2(aB1);
        float2 s2a = unpack2(aA2), s2b = unpack2(aB2);
        float2 s3a = unpack2(aA3), s3b = unpack2(aB3);
        float ai = s0a.x + s0a.y + s0b.x + s0b.y;
        float af = s1a.x + s1a.y + s1b.x + s1b.y;
        float ag = s2a.x + s2a.y + s2b.x + s2b.y;
        float ao = s3a.x + s3a.y + s3b.x + s3b.y;

        float gi = sigmoidf_(ai + xi);
        float gf = sigmoidf_(af + xf);
        float gG = tanhf   (ag + xG);
        float go = sigmoidf_(ao + xo);
        c_reg = gf * c_reg + gi * gG;
        float hv = go * tanhf(c_reg);

        __stcg(&g_h[rb ^ 1][hout_idx], hv);

        // Grid barrier: release-add + acquire-poll (no full membar).
        __syncthreads();
        if (tid == 0) {
            asm volatile("red.release.gpu.global.add.u32 [%0], 1;"
                         :: "l"(&g_bar) : "memory");
            const unsigned target = (unsigned)(t + 1) * NCTA;
            unsigned v;
            do {
                asm volatile("ld.acquire.gpu.global.u32 %0, [%1];"
                             : "=r"(v) : "l"(&g_bar) : "memory");
            } while (v < target);
        }
        __syncthreads();
    }
}

// Final FC: warp per output element (64*4 = 256 warps = 32 blocks).
__global__ void fc_kernel(const float* __restrict__ W_fc, const float* __restrict__ b_fc,
                          float* __restrict__ out) {
    const int warp = (blockIdx.x * blockDim.x + threadIdx.x) >> 5;
    const int lane = threadIdx.x & 31;
    const int b = warp >> 2, c = warp & 3;
    const float* h0 = g_h[0];
    const float* w  = W_fc + c * HID;
    float acc = 0.f;
    #pragma unroll 4
    for (int k = lane; k < HID; k += 32)
        acc += h0[(k >> 1) * 128 + b * 2 + (k & 1)] * w[k];
    #pragma unroll
    for (int off = 16; off; off >>= 1)
        acc += __shfl_xor_sync(0xFFFFFFFFu, acc, off);
    if (lane == 0) out[b * NCLS + c] = acc + b_fc[c];
}

extern "C" void kernel_launch(void* const* d_in, const int* in_sizes, int n_in,
                              void* d_out, int out_size) {
    const int*   x    = (const int*)  d_in[0];
    const float* emb  = (const float*)d_in[1];
    const float* W_ih = (const float*)d_in[2];
    const float* W_hh = (const float*)d_in[3];
    const float* b_ih = (const float*)d_in[4];
    const float* b_hh = (const float*)d_in[5];
    const float* W_fc = (const float*)d_in[6];
    const float* b_fc = (const float*)d_in[7];
    float* out = (float*)d_out;

    const int smem_bytes = (HID * BATCH + 16 * HID) * sizeof(float);  // 160 KiB
    cudaFuncSetAttribute(lstm_persistent,
                         cudaFuncAttributeMaxDynamicSharedMemorySize, smem_bytes);

    init_state<<<64, 512>>>();

    dim3 g1(G4 / 64, (SEQ * BATCH) / 64);   // 32 x 512 CTAs
    xg_gemm<<<g1, 256>>>(x, emb, W_ih, b_ih, b_hh);

    lstm_persistent<<<NCTA, 256, smem_bytes>>>(W_hh);

    fc_kernel<<<32, 256>>>(W_fc, b_fc, out);
}

// round 6
// speedup vs baseline: 1.5792x; 1.5792x over previous
#include <cuda_runtime.h>
#include <math.h>

#define BATCH 64
#define SEQ   512
#define EMB   256
#define HID   512
#define G4    2048   // 4*HID
#define NCLS  4
#define NCTA  128    // persistent CTAs, one per SM (<=148)
#define KCHUNK 128   // k-elements per pipeline chunk (4 chunks of 32KB)

// Scratch (allocation-free rule: __device__ globals)
__device__ float g_xg[(size_t)SEQ * G4 * BATCH];   // [t][n][b], n = gate*H + j  (256 MiB)
__device__ float g_h[2][HID * BATCH];              // [buf][j][b]  (transposed)
__device__ unsigned int g_bar;

__device__ __forceinline__ float sigmoidf_(float x) {
    return 1.0f / (1.0f + __expf(-x));
}

// cp.async.cg: 16B global->shared, L1-bypass (L2 only) — matches __ldcg semantics.
__device__ __forceinline__ void cp_async16(void* smem_dst, const void* gmem_src) {
    unsigned saddr = (unsigned)__cvta_generic_to_shared(smem_dst);
    asm volatile("cp.async.cg.shared.global [%0], [%1], 16;"
                 :: "r"(saddr), "l"(gmem_src) : "memory");
}
__device__ __forceinline__ void cp_async_commit() {
    asm volatile("cp.async.commit_group;" ::: "memory");
}
template <int N>
__device__ __forceinline__ void cp_async_wait() {
    asm volatile("cp.async.wait_group %0;" :: "n"(N) : "memory");
}

__global__ void init_state() {
    int i = blockIdx.x * blockDim.x + threadIdx.x;
    g_h[0][i] = 0.0f;
    if (i == 0) g_bar = 0u;
}

// xg[t][n][b] = sum_k emb[tok(t,b)][k] * W_ih[n][k] + b_ih[n] + b_hh[n]
// Tiled fp32 GEMM: 64x64 tile, BK=16, 256 threads, 4x4 micro-tile.
__global__ void xg_gemm(const int* __restrict__ x, const float* __restrict__ emb,
                        const float* __restrict__ W_ih,
                        const float* __restrict__ b_ih, const float* __restrict__ b_hh) {
    __shared__ float As[16][64];
    __shared__ float Bs[16][64];
    __shared__ int   tok_s[64];

    const int m0  = blockIdx.y * 64;
    const int n0  = blockIdx.x * 64;
    const int tid = threadIdx.x;        // 256
    const int tx  = tid & 15, ty = tid >> 4;
    const int r   = tid >> 2, q  = tid & 3;

    if (tid < 64) {
        int m = m0 + tid;
        tok_s[tid] = x[(m & (BATCH - 1)) * SEQ + (m >> 6)];
    }
    __syncthreads();

    const size_t arow = (size_t)tok_s[r] * EMB;
    const size_t brow = (size_t)(n0 + r) * EMB;

    float acc[4][4] = {};
    for (int kt = 0; kt < EMB; kt += 16) {
        float4 av = *(const float4*)(emb  + arow + kt + q * 4);
        float4 bv = *(const float4*)(W_ih + brow + kt + q * 4);
        As[q*4+0][r] = av.x; As[q*4+1][r] = av.y; As[q*4+2][r] = av.z; As[q*4+3][r] = av.w;
        Bs[q*4+0][r] = bv.x; Bs[q*4+1][r] = bv.y; Bs[q*4+2][r] = bv.z; Bs[q*4+3][r] = bv.w;
        __syncthreads();
        #pragma unroll
        for (int k = 0; k < 16; k++) {
            float4 a = *(const float4*)&As[k][ty * 4];
            float4 b = *(const float4*)&Bs[k][tx * 4];
            acc[0][0] += a.x*b.x; acc[0][1] += a.x*b.y; acc[0][2] += a.x*b.z; acc[0][3] += a.x*b.w;
            acc[1][0] += a.y*b.x; acc[1][1] += a.y*b.y; acc[1][2] += a.y*b.z; acc[1][3] += a.y*b.w;
            acc[2][0] += a.z*b.x; acc[2][1] += a.z*b.y; acc[2][2] += a.z*b.z; acc[2][3] += a.z*b.w;
            acc[3][0] += a.w*b.x; acc[3][1] += a.w*b.y; acc[3][2] += a.w*b.z; acc[3][3] += a.w*b.w;
        }
        __syncthreads();
    }

    // write [t][n][b] layout; within this block t is constant, b = ty*4+i.
    const int t = m0 >> 6;
    #pragma unroll
    for (int j = 0; j < 4; j++) {
        int n = n0 + tx * 4 + j;
        float bias = b_ih[n] + b_hh[n];
        float4 v = make_float4(acc[0][j] + bias, acc[1][j] + bias,
                               acc[2][j] + bias, acc[3][j] + bias);
        *(float4*)&g_xg[((size_t)t * G4 + n) * BATCH + ty * 4] = v;
    }
}

// Persistent recurrence: 128 CTAs (1/SM), each owns 4 hidden units (16 W_hh rows
// in smem). Per step, the 128KB h-broadcast is pipelined in 4 chunks via
// cp.async.cg so the copy overlaps the dot-product compute.
__global__ void __launch_bounds__(256, 1)
lstm_persistent(const float* __restrict__ W_hh) {
    extern __shared__ float sm[];
    float* h_s = sm;                    // [512][64]: h_s[k*64 + b]
    float* W_s = sm + HID * BATCH;      // [16][512]: row = gate*4 + unit

    const int tid = threadIdx.x;        // 256
    const int cta = blockIdx.x;
    const int b = tid & 63;
    const int r = tid >> 6;             // local unit 0..3
    const int j0 = cta * 4;
    const int j  = j0 + r;

    // One-time: load this CTA's 16 W_hh rows into smem.
    for (int row = 0; row < 16; row++) {
        int g = row >> 2, u = row & 3;
        const float* src = W_hh + (size_t)(g * HID + j0 + u) * HID;
        for (int k = tid; k < HID; k += 256)
            W_s[row * HID + k] = src[k];
    }
    float c_reg = 0.0f;
    __syncthreads();

    const float4* W4 = (const float4*)W_s;
    const float4* wi = W4 + (0 * 4 + r) * (HID / 4);
    const float4* wf = W4 + (1 * 4 + r) * (HID / 4);
    const float4* wg = W4 + (2 * 4 + r) * (HID / 4);
    const float4* wo = W4 + (3 * 4 + r) * (HID / 4);
    const int hout_idx = j * BATCH + b;

    // Per chunk: KCHUNK*64 floats = 2048 float4 / 256 threads = 8 cp.async each.
    for (int t = 0; t < SEQ; t++) {
        const int rb = t & 1;
        const float4* hsrc = (const float4*)g_h[rb];
        float4* hdst = (float4*)h_s;

        // Prefetch chunk 0.
        #pragma unroll
        for (int i = 0; i < 8; i++)
            cp_async16(hdst + tid + i * 256, hsrc + tid + i * 256);
        cp_async_commit();

        // Prefetch xg early — LDG latency overlaps chunk-0 copy.
        const float* xg = g_xg + ((size_t)t * G4 + j) * BATCH + b;
        float xi = __ldcg(xg + 0 * HID * BATCH);
        float xf = __ldcg(xg + 1 * HID * BATCH);
        float xG = __ldcg(xg + 2 * HID * BATCH);
        float xo = __ldcg(xg + 3 * HID * BATCH);

        float ai = 0.f, af = 0.f, ag = 0.f, ao = 0.f;
        const float* hb = h_s + b;

        #pragma unroll
        for (int ci = 0; ci < 4; ci++) {
            // Kick off next chunk before waiting on current one.
            if (ci < 3) {
                const int off = (ci + 1) * (KCHUNK * BATCH / 4);   // float4 units
                #pragma unroll
                for (int i = 0; i < 8; i++)
                    cp_async16(hdst + off + tid + i * 256, hsrc + off + tid + i * 256);
                cp_async_commit();
                cp_async_wait<1>();    // current chunk complete, next in flight
            } else {
                cp_async_wait<0>();
            }
            __syncthreads();

            const int k40 = ci * (KCHUNK / 4);
            #pragma unroll 8
            for (int k4 = k40; k4 < k40 + KCHUNK / 4; k4++) {
                float h0 = hb[k4 * 256];
                float h1 = hb[k4 * 256 + 64];
                float h2 = hb[k4 * 256 + 128];
                float h3 = hb[k4 * 256 + 192];
                float4 vi = wi[k4], vf = wf[k4], vg = wg[k4], vo = wo[k4];
                ai += vi.x*h0 + vi.y*h1 + vi.z*h2 + vi.w*h3;
                af += vf.x*h0 + vf.y*h1 + vf.z*h2 + vf.w*h3;
                ag += vg.x*h0 + vg.y*h1 + vg.z*h2 + vg.w*h3;
                ao += vo.x*h0 + vo.y*h1 + vo.z*h2 + vo.w*h3;
            }
            // No sync needed after compute: next chunk writes a different region,
            // and the pre-compute __syncthreads orders chunk reuse across steps
            // via the grid barrier below.
        }

        float gi = sigmoidf_(ai + xi);
        float gf = sigmoidf_(af + xf);
        float gG = tanhf   (ag + xG);
        float go = sigmoidf_(ao + xo);
        c_reg = gf * c_reg + gi * gG;
        float hv = go * tanhf(c_reg);

        __stcg(&g_h[rb ^ 1][hout_idx], hv);

        // Grid barrier (R3-proven form).
        __threadfence();
        __syncthreads();
        if (tid == 0) {
            atomicAdd(&g_bar, 1u);
            const unsigned target = (unsigned)(t + 1) * NCTA;
            while (*((volatile unsigned*)&g_bar) < target) { }
            __threadfence();
        }
        __syncthreads();
    }
}

// Final FC: warp per output element (64*4 = 256 warps = 32 blocks).
__global__ void fc_kernel(const float* __restrict__ W_fc, const float* __restrict__ b_fc,
                          float* __restrict__ out) {
    const int warp = (blockIdx.x * blockDim.x + threadIdx.x) >> 5;
    const int lane = threadIdx.x & 31;
    const int b = warp >> 2, c = warp & 3;
    const float* h0 = g_h[0];
    const float* w  = W_fc + c * HID;
    float acc = 0.f;
    #pragma unroll 4
    for (int k = lane; k < HID; k += 32)
        acc += h0[k * BATCH + b] * w[k];
    #pragma unroll
    for (int off = 16; off; off >>= 1)
        acc += __shfl_xor_sync(0xFFFFFFFFu, acc, off);
    if (lane == 0) out[b * NCLS + c] = acc + b_fc[c];
}

extern "C" void kernel_launch(void* const* d_in, const int* in_sizes, int n_in,
                              void* d_out, int out_size) {
    const int*   x    = (const int*)  d_in[0];
    const float* emb  = (const float*)d_in[1];
    const float* W_ih = (const float*)d_in[2];
    const float* W_hh = (const float*)d_in[3];
    const float* b_ih = (const float*)d_in[4];
    const float* b_hh = (const float*)d_in[5];
    const float* W_fc = (const float*)d_in[6];
    const float* b_fc = (const float*)d_in[7];
    float* out = (float*)d_out;

    const int smem_bytes = (HID * BATCH + 16 * HID) * sizeof(float);  // 160 KiB
    cudaFuncSetAttribute(lstm_persistent,
                         cudaFuncAttributeMaxDynamicSharedMemorySize, smem_bytes);

    init_state<<<64, 512>>>();

    dim3 g1(G4 / 64, (SEQ * BATCH) / 64);   // 32 x 512 CTAs
    xg_gemm<<<g1, 256>>>(x, emb, W_ih, b_ih, b_hh);

    lstm_persistent<<<NCTA, 256, smem_bytes>>>(W_hh);

    fc_kernel<<<32, 256>>>(W_fc, b_fc, out);
}

// round 8
// speedup vs baseline: 2.2806x; 1.4442x over previous
#include <cuda_runtime.h>
#include <math.h>
#include <stdint.h>

#define BATCH 64
#define SEQ   512
#define EMB   256
#define HID   512
#define G4    2048   // 4*HID
#define NCLS  4
#define NCTA  128    // persistent CTAs, one per SM
#define HPAD  68     // h_s row stride (floats): 64 + 4 pad (conflict-free frags)
#define WPAD  516    // W_s row stride (floats): 512 + 4 pad

// Scratch (allocation-free rule: __device__ globals)
__device__ float g_xg[(size_t)SEQ * G4 * BATCH];   // [t][n][b], n = gate*H + j
__device__ float g_h[2][HID * BATCH];              // [buf][k][b], tf32-bit floats
__device__ unsigned int g_bar;

__device__ __forceinline__ float sigmoidf_(float x) {
    return 1.0f / (1.0f + __expf(-x));
}
__device__ __forceinline__ uint32_t f2tf32(float f) {
    uint32_t u;
    asm("cvt.rna.tf32.f32 %0, %1;" : "=r"(u) : "f"(f));
    return u;
}
__device__ __forceinline__ void mma_tf32(float& d0, float& d1, float& d2, float& d3,
                                         uint32_t a0, uint32_t a1, uint32_t a2, uint32_t a3,
                                         uint32_t b0, uint32_t b1) {
    asm volatile("mma.sync.aligned.m16n8k8.row.col.f32.tf32.tf32.f32 "
                 "{%0,%1,%2,%3}, {%4,%5,%6,%7}, {%8,%9}, {%0,%1,%2,%3};"
                 : "+f"(d0), "+f"(d1), "+f"(d2), "+f"(d3)
                 : "r"(a0), "r"(a1), "r"(a2), "r"(a3), "r"(b0), "r"(b1));
}

// cp.async.cg: 16B global->shared, L1-bypass.
__device__ __forceinline__ void cp_async16(void* smem_dst, const void* gmem_src) {
    unsigned saddr = (unsigned)__cvta_generic_to_shared(smem_dst);
    asm volatile("cp.async.cg.shared.global [%0], [%1], 16;"
                 :: "r"(saddr), "l"(gmem_src) : "memory");
}
__device__ __forceinline__ void cp_async_commit() {
    asm volatile("cp.async.commit_group;" ::: "memory");
}
template <int N>
__device__ __forceinline__ void cp_async_wait() {
    asm volatile("cp.async.wait_group %0;" :: "n"(N) : "memory");
}

__global__ void init_state() {
    int i = blockIdx.x * blockDim.x + threadIdx.x;
    g_h[0][i] = 0.0f;
    if (i == 0) g_bar = 0u;
}

// ============================================================================
// xg_gemm (tf32 mma): xg[t][n][b] = sum_k emb[tok(t,b)][k]*W_ih[n][k] + bias[n]
// CTA tile: 64(m=b) x 64(n), K=256 in 8 stages of 32. 256 threads = 8 warps,
// warp = 16m x 32n (1 m-tile x 4 n-subtiles). Grid (32 n-tiles, 512 t).
// ============================================================================
__global__ void __launch_bounds__(256)
xg_gemm(const int* __restrict__ x, const float* __restrict__ emb,
        const float* __restrict__ W_ih,
        const float* __restrict__ b_ih, const float* __restrict__ b_hh) {
    __shared__ float As[32][HPAD];   // [k][m], tf32 bits
    __shared__ float Bs[32][HPAD];   // [k][n], tf32 bits
    __shared__ int   tok_s[64];
    __shared__ float sbias[64];

    const int t    = blockIdx.y;
    const int ncta = blockIdx.x * 64;
    const int tid  = threadIdx.x;          // 256
    const int warp = tid >> 5;
    const int lane = tid & 31;
    const int gid  = lane >> 2;            // 0..7
    const int tig  = lane & 3;             // 0..3
    const int wm   = warp & 3;             // m-tile (16 rows)
    const int wn   = warp >> 2;            // 0..1 (32 n each)
    const int m0   = wm * 16;

    if (tid < 64) {
        tok_s[tid] = x[tid * SEQ + t];
        int n = ncta + tid;
        sbias[tid] = b_ih[n] + b_hh[n];
    }
    __syncthreads();

    const uint32_t* Asu = (const uint32_t*)As;
    const uint32_t* Bsu = (const uint32_t*)Bs;

    float d[4][4] = {};   // [nt][reg]

    for (int kt = 0; kt < EMB; kt += 32) {
        // Stage: 64 rows x 32 k for A and B; 512 float4 each / 256 thr = 2 each.
        #pragma unroll
        for (int jj = 0; jj < 2; jj++) {
            int idx = tid + jj * 256;       // 0..511
            int row = idx >> 3, qk = idx & 7;
            float4 av = *(const float4*)(emb + (size_t)tok_s[row] * EMB + kt + qk * 4);
            As[qk*4+0][row] = __uint_as_float(f2tf32(av.x));
            As[qk*4+1][row] = __uint_as_float(f2tf32(av.y));
            As[qk*4+2][row] = __uint_as_float(f2tf32(av.z));
            As[qk*4+3][row] = __uint_as_float(f2tf32(av.w));
            float4 bv = *(const float4*)(W_ih + (size_t)(ncta + row) * EMB + kt + qk * 4);
            Bs[qk*4+0][row] = __uint_as_float(f2tf32(bv.x));
            Bs[qk*4+1][row] = __uint_as_float(f2tf32(bv.y));
            Bs[qk*4+2][row] = __uint_as_float(f2tf32(bv.z));
            Bs[qk*4+3][row] = __uint_as_float(f2tf32(bv.w));
        }
        __syncthreads();

        #pragma unroll
        for (int s = 0; s < 4; s++) {
            const int k0 = s * 8;
            uint32_t a0 = Asu[(k0 + tig)     * HPAD + m0 + gid];
            uint32_t a1 = Asu[(k0 + tig)     * HPAD + m0 + gid + 8];
            uint32_t a2 = Asu[(k0 + tig + 4) * HPAD + m0 + gid];
            uint32_t a3 = Asu[(k0 + tig + 4) * HPAD + m0 + gid + 8];
            #pragma unroll
            for (int nt = 0; nt < 4; nt++) {
                const int n0 = wn * 32 + nt * 8;
                uint32_t b0 = Bsu[(k0 + tig)     * HPAD + n0 + gid];
                uint32_t b1 = Bsu[(k0 + tig + 4) * HPAD + n0 + gid];
                mma_tf32(d[nt][0], d[nt][1], d[nt][2], d[nt][3],
                         a0, a1, a2, a3, b0, b1);
            }
        }
        __syncthreads();
    }

    // Epilogue: D[m][n] -> g_xg[t][ncta+n][m] + bias.
    #pragma unroll
    for (int nt = 0; nt < 4; nt++) {
        const int na = wn * 32 + nt * 8 + 2 * tig;
        const int nb = na + 1;
        const int r0 = m0 + gid;
        const int r1 = r0 + 8;
        g_xg[((size_t)t * G4 + ncta + na) * BATCH + r0] = d[nt][0] + sbias[na];
        g_xg[((size_t)t * G4 + ncta + nb) * BATCH + r0] = d[nt][1] + sbias[nb];
        g_xg[((size_t)t * G4 + ncta + na) * BATCH + r1] = d[nt][2] + sbias[na];
        g_xg[((size_t)t * G4 + ncta + nb) * BATCH + r1] = d[nt][3] + sbias[nb];
    }
}

// ============================================================================
// Persistent recurrence with tf32 mma. 128 CTAs x 512 threads (16 warps).
// Per step: gate GEMM D[64 b][16 n] = h[64][512] @ W_cta[16][512]^T via
// m16n8k8 tiles. Warp = (wm: 4 m-tiles, wn: 2 n-tiles, kh: split-K 2).
// h broadcast in 4 cp.async chunks overlapped with compute.
// ============================================================================
__global__ void __launch_bounds__(512, 1)
lstm_persistent(const float* __restrict__ W_hh) {
    extern __shared__ float sm[];
    float* h_s = sm;                          // [512][HPAD] tf32 bits
    float* W_s = sm + HID * HPAD;             // [16][WPAD]  tf32 bits
    float* pre = W_s + 16 * WPAD;             // [2 kh][16 n][HPAD]

    const int tid  = threadIdx.x;             // 512
    const int cta  = blockIdx.x;
    const int warp = tid >> 5;
    const int lane = tid & 31;
    const int gid  = lane >> 2;
    const int tig  = lane & 3;
    const int wm   = warp & 3;                // m-tile: m0 = wm*16
    const int wn   = (warp >> 2) & 1;         // n-tile: n0 = wn*8
    const int kh   = warp >> 3;               // split-K half
    const int m0   = wm * 16;
    const int n0   = wn * 8;
    const int j0   = cta * 4;

    // One-time: 16 W_hh rows -> smem as tf32.
    #pragma unroll
    for (int row = 0; row < 16; row++) {
        int g = row >> 2, u = row & 3;
        W_s[row * WPAD + tid] = __uint_as_float(
            f2tf32(W_hh[(size_t)(g * HID + j0 + u) * HID + tid]));
    }
    float c_reg = 0.0f;
    __syncthreads();

    const uint32_t* Hsu = (const uint32_t*)h_s;
    const uint32_t* Wsu = (const uint32_t*)W_s;

    // epilogue identity (tid<256): b, unit
    const int eb = tid & 63;
    const int eu = (tid >> 6) & 3;

    for (int t = 0; t < SEQ; t++) {
        const int rb = t & 1;
        const float4* hsrc = (const float4*)g_h[rb];

        // Prefetch chunk 0 (128 k rows -> padded h_s rows).
        {
            #pragma unroll
            for (int i = 0; i < 4; i++) {
                int p = tid + i * 512;            // piece 0..2047
                int krow = p >> 4, sub = p & 15;
                cp_async16(h_s + krow * HPAD + sub * 4, hsrc + p);
            }
            cp_async_commit();
        }

        // Prefetch xg (only epilogue threads need it).
        float xi = 0.f, xf = 0.f, xG = 0.f, xo = 0.f;
        if (tid < 256) {
            const float* xg = g_xg + ((size_t)t * G4 + j0 + eu) * BATCH + eb;
            xi = __ldcg(xg + 0 * HID * BATCH);
            xf = __ldcg(xg + 1 * HID * BATCH);
            xG = __ldcg(xg + 2 * HID * BATCH);
            xo = __ldcg(xg + 3 * HID * BATCH);
        }

        float d0 = 0.f, d1 = 0.f, d2 = 0.f, d3 = 0.f;

        #pragma unroll
        for (int ci = 0; ci < 4; ci++) {
            if (ci < 3) {
                const int base = (ci + 1) * 2048;
                #pragma unroll
                for (int i = 0; i < 4; i++) {
                    int p = tid + i * 512;
                    int krow = ((base + p) >> 4), sub = p & 15;
                    cp_async16(h_s + krow * HPAD + sub * 4, hsrc + base + p);
                }
                cp_async_commit();
                cp_async_wait<1>();
            } else {
                cp_async_wait<0>();
            }
            __syncthreads();

            const int ks0 = ci * 16 + kh * 8;
            #pragma unroll
            for (int s = 0; s < 8; s++) {
                const int k0 = (ks0 + s) * 8;
                uint32_t a0 = Hsu[(k0 + tig)     * HPAD + m0 + gid];
                uint32_t a1 = Hsu[(k0 + tig)     * HPAD + m0 + gid + 8];
                uint32_t a2 = Hsu[(k0 + tig + 4) * HPAD + m0 + gid];
                uint32_t a3 = Hsu[(k0 + tig + 4) * HPAD + m0 + gid + 8];
                uint32_t b0 = Wsu[(n0 + gid) * WPAD + k0 + tig];
                uint32_t b1 = Wsu[(n0 + gid) * WPAD + k0 + tig + 4];
                mma_tf32(d0, d1, d2, d3, a0, a1, a2, a3, b0, b1);
            }
        }

        // Store split-K partials: pre[kh][n][b].
        {
            const int na = n0 + 2 * tig;
            const int r0 = m0 + gid;
            pre[(kh * 16 + na)     * HPAD + r0]     = d0;
            pre[(kh * 16 + na + 1) * HPAD + r0]     = d1;
            pre[(kh * 16 + na)     * HPAD + r0 + 8] = d2;
            pre[(kh * 16 + na + 1) * HPAD + r0 + 8] = d3;
        }
        __syncthreads();

        if (tid < 256) {
            const int b = eb, u = eu;
            float ai = pre[(0 * 4 + u) * HPAD + b] + pre[(16 + 0 * 4 + u) * HPAD + b];
            float af = pre[(1 * 4 + u) * HPAD + b] + pre[(16 + 1 * 4 + u) * HPAD + b];
            float ag = pre[(2 * 4 + u) * HPAD + b] + pre[(16 + 2 * 4 + u) * HPAD + b];
            float ao = pre[(3 * 4 + u) * HPAD + b] + pre[(16 + 3 * 4 + u) * HPAD + b];

            float gi = sigmoidf_(ai + xi);
            float gf = sigmoidf_(af + xf);
            float gG = tanhf   (ag + xG);
            float go = sigmoidf_(ao + xo);
            c_reg = gf * c_reg + gi * gG;
            float hv = go * tanhf(c_reg);

            __stcg(&g_h[rb ^ 1][(j0 + u) * BATCH + b],
                   __uint_as_float(f2tf32(hv)));
        }

        // Grid barrier.
        __threadfence();
        __syncthreads();
        if (tid == 0) {
            atomicAdd(&g_bar, 1u);
            const unsigned target = (unsigned)(t + 1) * NCTA;
            while (*((volatile unsigned*)&g_bar) < target) { }
            __threadfence();
        }
        __syncthreads();
    }
}

// Final FC: warp per output element (64*4 = 256 warps = 32 blocks).
__global__ void fc_kernel(const float* __restrict__ W_fc, const float* __restrict__ b_fc,
                          float* __restrict__ out) {
    const int warp = (blockIdx.x * blockDim.x + threadIdx.x) >> 5;
    const int lane = threadIdx.x & 31;
    const int b = warp >> 2, c = warp & 3;
    const float* h0 = g_h[0];
    const float* w  = W_fc + c * HID;
    float acc = 0.f;
    #pragma unroll 4
    for (int k = lane; k < HID; k += 32)
        acc += h0[k * BATCH + b] * w[k];
    #pragma unroll
    for (int off = 16; off; off >>= 1)
        acc += __shfl_xor_sync(0xFFFFFFFFu, acc, off);
    if (lane == 0) out[b * NCLS + c] = acc + b_fc[c];
}

extern "C" void kernel_launch(void* const* d_in, const int* in_sizes, int n_in,
                              void* d_out, int out_size) {
    const int*   x    = (const int*)  d_in[0];
    const float* emb  = (const float*)d_in[1];
    const float* W_ih = (const float*)d_in[2];
    const float* W_hh = (const float*)d_in[3];
    const float* b_ih = (const float*)d_in[4];
    const float* b_hh = (const float*)d_in[5];
    const float* W_fc = (const float*)d_in[6];
    const float* b_fc = (const float*)d_in[7];
    float* out = (float*)d_out;

    const int smem_bytes = (HID * HPAD + 16 * WPAD + 2 * 16 * HPAD) * sizeof(float); // ~177 KiB
    cudaFuncSetAttribute(lstm_persistent,
                         cudaFuncAttributeMaxDynamicSharedMemorySize, smem_bytes);

    init_state<<<64, 512>>>();

    dim3 g1(G4 / 64, SEQ);   // 32 x 512 CTAs
    xg_gemm<<<g1, 256>>>(x, emb, W_ih, b_ih, b_hh);

    lstm_persistent<<<NCTA, 512, smem_bytes>>>(W_hh);

    fc_kernel<<<32, 256>>>(W_fc, b_fc, out);
}